// round 8
// baseline (speedup 1.0000x reference)
#include <cuda_runtime.h>

// Problem constants
#define B_   8
#define S_   4096
#define H_   1024
#define D_   64
#define BSROWS (B_ * S_)   // 32768 rows

// Scratch Q/K/V (device globals — no allocation allowed).
// Stored as float4 rows: each row = 64 floats = 16 float4.
__device__ float4 g_Q[BSROWS * 16];
__device__ float4 g_K[BSROWS * 16];
__device__ float4 g_V[BSROWS * 16];

// XOR swizzle at float4 granularity: tile is [64 rows][16 float4 cols].
// Permutes col4 by (row & 15) -> conflict-light LDS.128 in both GEMM shapes.
__device__ __forceinline__ int sw(int row, int c4) {
    return row * 16 + (c4 ^ (row & 15));
}

// ---------------------------------------------------------------------------
// Kernel 1: QKV projection.  out[r][d] = sum_h x[r][h] * W[h][d] + b[d]
// grid = (BSROWS/64, 3), block = 256.  64x64 output tile, K-loop over 1024.
// ---------------------------------------------------------------------------
__global__ __launch_bounds__(256, 2)
void qkv_kernel(const float4* __restrict__ x,
                const float4* __restrict__ Wq, const float* __restrict__ bq,
                const float4* __restrict__ Wk, const float* __restrict__ bk,
                const float4* __restrict__ Wv, const float* __restrict__ bv)
{
    __shared__ float4 As[64 * 16];   // x tile   [row][k]  (swizzled)
    __shared__ float4 Bs[64 * 16];   // W tile   [k][d]    (swizzled)

    const int tid = threadIdx.x;
    const int ty  = tid >> 4;        // 0..15 -> output rows ty*4..ty*4+3
    const int tx  = tid & 15;        // 0..15 -> output cols tx*4..tx*4+3
    const int r0  = blockIdx.x * 64;

    const float4* W; const float* bias; float4* out;
    if (blockIdx.y == 0)      { W = Wq; bias = bq; out = g_Q; }
    else if (blockIdx.y == 1) { W = Wk; bias = bk; out = g_K; }
    else                      { W = Wv; bias = bv; out = g_V; }

    float acc[4][4];
#pragma unroll
    for (int i = 0; i < 4; ++i)
#pragma unroll
        for (int j = 0; j < 4; ++j) acc[i][j] = 0.0f;

    for (int kt = 0; kt < 16; ++kt) {       // 16 tiles of 64 over H=1024
        __syncthreads();                     // protect previous tiles
#pragma unroll
        for (int p = 0; p < 4; ++p) {
            int idx = tid + p * 256;         // 1024 float4 per tile
            int row = idx >> 4, c4 = idx & 15;
            // x row = H=1024 floats = 256 float4; tile k-offset = kt*16 f4
            As[sw(row, c4)] = x[(size_t)(r0 + row) * 256 + kt * 16 + c4];
            // W row = 64 floats = 16 float4
            Bs[sw(row, c4)] = W[(size_t)(kt * 64 + row) * 16 + c4];
        }
        __syncthreads();

#pragma unroll 4
        for (int k4 = 0; k4 < 16; ++k4) {
            float4 a4[4], b4[4];
#pragma unroll
            for (int i = 0; i < 4; ++i) a4[i] = As[sw(ty * 4 + i, k4)];
#pragma unroll
            for (int kk = 0; kk < 4; ++kk) b4[kk] = Bs[sw(k4 * 4 + kk, tx)];
#pragma unroll
            for (int i = 0; i < 4; ++i) {
                acc[i][0] += a4[i].x*b4[0].x + a4[i].y*b4[1].x + a4[i].z*b4[2].x + a4[i].w*b4[3].x;
                acc[i][1] += a4[i].x*b4[0].y + a4[i].y*b4[1].y + a4[i].z*b4[2].y + a4[i].w*b4[3].y;
                acc[i][2] += a4[i].x*b4[0].z + a4[i].y*b4[1].z + a4[i].z*b4[2].z + a4[i].w*b4[3].z;
                acc[i][3] += a4[i].x*b4[0].w + a4[i].y*b4[1].w + a4[i].z*b4[2].w + a4[i].w*b4[3].w;
            }
        }
    }

    const float b0 = bias[tx * 4 + 0], b1 = bias[tx * 4 + 1];
    const float b2 = bias[tx * 4 + 2], b3 = bias[tx * 4 + 3];
#pragma unroll
    for (int i = 0; i < 4; ++i) {
        int row = r0 + ty * 4 + i;
        out[(size_t)row * 16 + tx] =
            make_float4(acc[i][0] + b0, acc[i][1] + b1, acc[i][2] + b2, acc[i][3] + b3);
    }
}

// ---------------------------------------------------------------------------
// Kernel 2: causal flash attention, fp32.  Br=Bc=64, D=64.
// grid = (S/64, B), block = 256 (16x16; each thread owns 4x4 of S and O).
// S-tile rows map to half-warps -> 16-lane shfl reductions for softmax.
// P is written back into the K smem buffer (keeps static smem at 48KB).
// ---------------------------------------------------------------------------
__global__ __launch_bounds__(256, 2)
void attn_kernel(float4* __restrict__ out)
{
    __shared__ float4 Qs[64 * 16];
    __shared__ float4 Ks[64 * 16];   // reused as P after S is computed
    __shared__ float4 Vs[64 * 16];

    const int tid = threadIdx.x;
    const int ty  = tid >> 4;
    const int tx  = tid & 15;
    const int qt  = (int)(gridDim.x - 1) - (int)blockIdx.x;  // heavy blocks first
    const int b   = blockIdx.y;
    const int q0  = qt * 64;
    const size_t base = (size_t)b * S_;      // row base into g_Q/g_K/g_V

    // Load Q tile once
#pragma unroll
    for (int p = 0; p < 4; ++p) {
        int idx = tid + p * 256;
        int row = idx >> 4, c4 = idx & 15;
        Qs[sw(row, c4)] = g_Q[(base + q0 + row) * 16 + c4];
    }

    float o[4][4];
    float m[4], l[4];
#pragma unroll
    for (int i = 0; i < 4; ++i) {
        m[i] = -1e30f; l[i] = 0.0f;
#pragma unroll
        for (int j = 0; j < 4; ++j) o[i][j] = 0.0f;
    }
    const float scale = 0.125f;   // 1/sqrt(64)

    for (int t = 0; t <= qt; ++t) {
        const int k0 = t * 64;
        __syncthreads();          // previous-iter smem reads complete
#pragma unroll
        for (int p = 0; p < 4; ++p) {
            int idx = tid + p * 256;
            int row = idx >> 4, c4 = idx & 15;
            Ks[sw(row, c4)] = g_K[(base + k0 + row) * 16 + c4];
            Vs[sw(row, c4)] = g_V[(base + k0 + row) * 16 + c4];
        }
        __syncthreads();

        // ---- S = Q K^T (both K-major; dot along d) ----
        float s[4][4];
#pragma unroll
        for (int i = 0; i < 4; ++i)
#pragma unroll
            for (int j = 0; j < 4; ++j) s[i][j] = 0.0f;

#pragma unroll 4
        for (int k4 = 0; k4 < 16; ++k4) {
            float4 a4[4], b4[4];
#pragma unroll
            for (int i = 0; i < 4; ++i) a4[i] = Qs[sw(ty * 4 + i, k4)];
#pragma unroll
            for (int j = 0; j < 4; ++j) b4[j] = Ks[sw(tx * 4 + j, k4)];
#pragma unroll
            for (int i = 0; i < 4; ++i)
#pragma unroll
                for (int j = 0; j < 4; ++j)
                    s[i][j] += a4[i].x*b4[j].x + a4[i].y*b4[j].y
                             + a4[i].z*b4[j].z + a4[i].w*b4[j].w;
        }

        // ---- causal mask (diagonal tile only; q0 == k0 there) ----
        if (t == qt) {
#pragma unroll
            for (int i = 0; i < 4; ++i)
#pragma unroll
                for (int j = 0; j < 4; ++j)
                    if (tx * 4 + j > ty * 4 + i) s[i][j] = -1e30f;
        }

        // ---- online softmax (scale folded into exp) ----
#pragma unroll
        for (int i = 0; i < 4; ++i) {
            float rm = fmaxf(fmaxf(s[i][0], s[i][1]), fmaxf(s[i][2], s[i][3]));
#pragma unroll
            for (int off = 1; off < 16; off <<= 1)
                rm = fmaxf(rm, __shfl_xor_sync(0xffffffffu, rm, off, 16));
            const float mn = fmaxf(m[i], rm);
            const float alpha = __expf(scale * (m[i] - mn));
            m[i] = mn;
            float rs = 0.0f;
#pragma unroll
            for (int j = 0; j < 4; ++j) {
                s[i][j] = __expf(scale * (s[i][j] - mn));   // s becomes P
                rs += s[i][j];
            }
#pragma unroll
            for (int off = 1; off < 16; off <<= 1)
                rs += __shfl_xor_sync(0xffffffffu, rs, off, 16);
            l[i] = l[i] * alpha + rs;
#pragma unroll
            for (int j = 0; j < 4; ++j) o[i][j] *= alpha;
        }

        __syncthreads();          // all warps done reading Ks as K
        // ---- store P into Ks buffer (thread owns rows ty*4+i, f4-col tx) ----
#pragma unroll
        for (int i = 0; i < 4; ++i)
            Ks[sw(ty * 4 + i, tx)] = make_float4(s[i][0], s[i][1], s[i][2], s[i][3]);
        __syncthreads();

        // ---- O += P @ V ----
#pragma unroll 4
        for (int k4 = 0; k4 < 16; ++k4) {
            float4 p4[4], v4[4];
#pragma unroll
            for (int i = 0; i < 4; ++i) p4[i] = Ks[sw(ty * 4 + i, k4)];
#pragma unroll
            for (int kk = 0; kk < 4; ++kk) v4[kk] = Vs[sw(k4 * 4 + kk, tx)];
#pragma unroll
            for (int i = 0; i < 4; ++i) {
                o[i][0] += p4[i].x*v4[0].x + p4[i].y*v4[1].x + p4[i].z*v4[2].x + p4[i].w*v4[3].x;
                o[i][1] += p4[i].x*v4[0].y + p4[i].y*v4[1].y + p4[i].z*v4[2].y + p4[i].w*v4[3].y;
                o[i][2] += p4[i].x*v4[0].z + p4[i].y*v4[1].z + p4[i].z*v4[2].z + p4[i].w*v4[3].z;
                o[i][3] += p4[i].x*v4[0].w + p4[i].y*v4[1].w + p4[i].z*v4[2].w + p4[i].w*v4[3].w;
            }
        }
    }

    // ---- epilogue: normalize and store ----
#pragma unroll
    for (int i = 0; i < 4; ++i) {
        const float inv = 1.0f / l[i];
        const int row = q0 + ty * 4 + i;
        out[(base + row) * 16 + tx] =
            make_float4(o[i][0] * inv, o[i][1] * inv, o[i][2] * inv, o[i][3] * inv);
    }
}

// ---------------------------------------------------------------------------
// Launch
// ---------------------------------------------------------------------------
extern "C" void kernel_launch(void* const* d_in, const int* in_sizes, int n_in,
                              void* d_out, int out_size)
{
    (void)in_sizes; (void)n_in; (void)out_size;
    const float4* x  = (const float4*)d_in[0];
    const float4* Wq = (const float4*)d_in[1];
    const float*  bq = (const float*) d_in[2];
    const float4* Wk = (const float4*)d_in[3];
    const float*  bk = (const float*) d_in[4];
    const float4* Wv = (const float4*)d_in[5];
    const float*  bv = (const float*) d_in[6];

    dim3 g1(BSROWS / 64, 3);
    qkv_kernel<<<g1, 256>>>(x, Wq, bq, Wk, bk, Wv, bv);

    dim3 g2(S_ / 64, B_);
    attn_kernel<<<g2, 256>>>((float4*)d_out);
}

// round 9
// speedup vs baseline: 1.2534x; 1.2534x over previous
#include <cuda_runtime.h>

// Problem constants
#define B_   8
#define S_   4096
#define H_   1024
#define D_   64
#define BSROWS (B_ * S_)   // 32768 rows

// Scratch Q/K/V (device globals — no allocation allowed).
// Stored as float4 rows: each row = 64 floats = 16 float4.
__device__ float4 g_Q[BSROWS * 16];
__device__ float4 g_K[BSROWS * 16];
__device__ float4 g_V[BSROWS * 16];

// XOR swizzle at float4 granularity, keyed on the ROW QUAD (row>>2).
// Column-direction accesses in the S=QK^T phase have lanes stepping 4 rows
// apart (row = tx*4+j), so keying on row>>2 = tx spreads the 32 lanes across
// all 8 bank groups (4 crossbar phases per LDS.128 = structural floor).
// The old (row & 15) key collapsed them into 2 groups (16 phases).
__device__ __forceinline__ int sw(int row, int c4) {
    return row * 16 + (c4 ^ ((row >> 2) & 15));
}

// ---------------------------------------------------------------------------
// Kernel 1: QKV projection.  out[r][d] = sum_h x[r][h] * W[h][d] + b[d]
// grid = (BSROWS/64, 3), block = 256.  64x64 output tile, K-loop over 1024.
// ---------------------------------------------------------------------------
__global__ __launch_bounds__(256, 2)
void qkv_kernel(const float4* __restrict__ x,
                const float4* __restrict__ Wq, const float* __restrict__ bq,
                const float4* __restrict__ Wk, const float* __restrict__ bk,
                const float4* __restrict__ Wv, const float* __restrict__ bv)
{
    __shared__ float4 As[64 * 16];   // x tile   [row][k]  (swizzled)
    __shared__ float4 Bs[64 * 16];   // W tile   [k][d]    (swizzled)

    const int tid = threadIdx.x;
    const int ty  = tid >> 4;        // 0..15 -> output rows ty*4..ty*4+3
    const int tx  = tid & 15;        // 0..15 -> output cols tx*4..tx*4+3
    const int r0  = blockIdx.x * 64;

    const float4* W; const float* bias; float4* out;
    if (blockIdx.y == 0)      { W = Wq; bias = bq; out = g_Q; }
    else if (blockIdx.y == 1) { W = Wk; bias = bk; out = g_K; }
    else                      { W = Wv; bias = bv; out = g_V; }

    float acc[4][4];
#pragma unroll
    for (int i = 0; i < 4; ++i)
#pragma unroll
        for (int j = 0; j < 4; ++j) acc[i][j] = 0.0f;

    for (int kt = 0; kt < 16; ++kt) {       // 16 tiles of 64 over H=1024
        __syncthreads();                     // protect previous tiles
#pragma unroll
        for (int p = 0; p < 4; ++p) {
            int idx = tid + p * 256;         // 1024 float4 per tile
            int row = idx >> 4, c4 = idx & 15;
            // x row = H=1024 floats = 256 float4; tile k-offset = kt*16 f4
            As[sw(row, c4)] = x[(size_t)(r0 + row) * 256 + kt * 16 + c4];
            // W row = 64 floats = 16 float4
            Bs[sw(row, c4)] = W[(size_t)(kt * 64 + row) * 16 + c4];
        }
        __syncthreads();

#pragma unroll 4
        for (int k4 = 0; k4 < 16; ++k4) {
            float4 a4[4], b4[4];
#pragma unroll
            for (int i = 0; i < 4; ++i) a4[i] = As[sw(ty * 4 + i, k4)];
#pragma unroll
            for (int kk = 0; kk < 4; ++kk) b4[kk] = Bs[sw(k4 * 4 + kk, tx)];
#pragma unroll
            for (int i = 0; i < 4; ++i) {
                acc[i][0] += a4[i].x*b4[0].x + a4[i].y*b4[1].x + a4[i].z*b4[2].x + a4[i].w*b4[3].x;
                acc[i][1] += a4[i].x*b4[0].y + a4[i].y*b4[1].y + a4[i].z*b4[2].y + a4[i].w*b4[3].y;
                acc[i][2] += a4[i].x*b4[0].z + a4[i].y*b4[1].z + a4[i].z*b4[2].z + a4[i].w*b4[3].z;
                acc[i][3] += a4[i].x*b4[0].w + a4[i].y*b4[1].w + a4[i].z*b4[2].w + a4[i].w*b4[3].w;
            }
        }
    }

    const float b0 = bias[tx * 4 + 0], b1 = bias[tx * 4 + 1];
    const float b2 = bias[tx * 4 + 2], b3 = bias[tx * 4 + 3];
#pragma unroll
    for (int i = 0; i < 4; ++i) {
        int row = r0 + ty * 4 + i;
        out[(size_t)row * 16 + tx] =
            make_float4(acc[i][0] + b0, acc[i][1] + b1, acc[i][2] + b2, acc[i][3] + b3);
    }
}

// ---------------------------------------------------------------------------
// Kernel 2: causal flash attention, fp32.  Br=Bc=64, D=64.
// grid = (S/64, B), block = 256 (16x16; each thread owns 4x4 of S and O).
// S-tile rows map to half-warps -> 16-lane shfl reductions for softmax.
// P is written back into the K smem buffer (keeps static smem at 48KB).
// ---------------------------------------------------------------------------
__global__ __launch_bounds__(256, 2)
void attn_kernel(float4* __restrict__ out)
{
    __shared__ float4 Qs[64 * 16];
    __shared__ float4 Ks[64 * 16];   // reused as P after S is computed
    __shared__ float4 Vs[64 * 16];

    const int tid = threadIdx.x;
    const int ty  = tid >> 4;
    const int tx  = tid & 15;
    const int qt  = (int)(gridDim.x - 1) - (int)blockIdx.x;  // heavy blocks first
    const int b   = blockIdx.y;
    const int q0  = qt * 64;
    const size_t base = (size_t)b * S_;      // row base into g_Q/g_K/g_V

    // Load Q tile once
#pragma unroll
    for (int p = 0; p < 4; ++p) {
        int idx = tid + p * 256;
        int row = idx >> 4, c4 = idx & 15;
        Qs[sw(row, c4)] = g_Q[(base + q0 + row) * 16 + c4];
    }

    float o[4][4];
    float m[4], l[4];
#pragma unroll
    for (int i = 0; i < 4; ++i) {
        m[i] = -1e30f; l[i] = 0.0f;
#pragma unroll
        for (int j = 0; j < 4; ++j) o[i][j] = 0.0f;
    }
    const float scale = 0.125f;   // 1/sqrt(64)

    for (int t = 0; t <= qt; ++t) {
        const int k0 = t * 64;
        __syncthreads();          // previous-iter smem reads complete
#pragma unroll
        for (int p = 0; p < 4; ++p) {
            int idx = tid + p * 256;
            int row = idx >> 4, c4 = idx & 15;
            Ks[sw(row, c4)] = g_K[(base + k0 + row) * 16 + c4];
            Vs[sw(row, c4)] = g_V[(base + k0 + row) * 16 + c4];
        }
        __syncthreads();

        // ---- S = Q K^T (both K-major; dot along d) ----
        float s[4][4];
#pragma unroll
        for (int i = 0; i < 4; ++i)
#pragma unroll
            for (int j = 0; j < 4; ++j) s[i][j] = 0.0f;

#pragma unroll 4
        for (int k4 = 0; k4 < 16; ++k4) {
            float4 a4[4], b4[4];
#pragma unroll
            for (int i = 0; i < 4; ++i) a4[i] = Qs[sw(ty * 4 + i, k4)];
#pragma unroll
            for (int j = 0; j < 4; ++j) b4[j] = Ks[sw(tx * 4 + j, k4)];
#pragma unroll
            for (int i = 0; i < 4; ++i)
#pragma unroll
                for (int j = 0; j < 4; ++j)
                    s[i][j] += a4[i].x*b4[j].x + a4[i].y*b4[j].y
                             + a4[i].z*b4[j].z + a4[i].w*b4[j].w;
        }

        // ---- causal mask (diagonal tile only; q0 == k0 there) ----
        if (t == qt) {
#pragma unroll
            for (int i = 0; i < 4; ++i)
#pragma unroll
                for (int j = 0; j < 4; ++j)
                    if (tx * 4 + j > ty * 4 + i) s[i][j] = -1e30f;
        }

        // ---- online softmax (scale folded into exp) ----
#pragma unroll
        for (int i = 0; i < 4; ++i) {
            float rm = fmaxf(fmaxf(s[i][0], s[i][1]), fmaxf(s[i][2], s[i][3]));
#pragma unroll
            for (int off = 1; off < 16; off <<= 1)
                rm = fmaxf(rm, __shfl_xor_sync(0xffffffffu, rm, off, 16));
            const float mn = fmaxf(m[i], rm);
            const float alpha = __expf(scale * (m[i] - mn));
            m[i] = mn;
            float rs = 0.0f;
#pragma unroll
            for (int j = 0; j < 4; ++j) {
                s[i][j] = __expf(scale * (s[i][j] - mn));   // s becomes P
                rs += s[i][j];
            }
#pragma unroll
            for (int off = 1; off < 16; off <<= 1)
                rs += __shfl_xor_sync(0xffffffffu, rs, off, 16);
            l[i] = l[i] * alpha + rs;
#pragma unroll
            for (int j = 0; j < 4; ++j) o[i][j] *= alpha;
        }

        __syncthreads();          // all warps done reading Ks as K
        // ---- store P into Ks buffer (thread owns rows ty*4+i, f4-col tx) ----
#pragma unroll
        for (int i = 0; i < 4; ++i)
            Ks[sw(ty * 4 + i, tx)] = make_float4(s[i][0], s[i][1], s[i][2], s[i][3]);
        __syncthreads();

        // ---- O += P @ V ----
#pragma unroll 4
        for (int k4 = 0; k4 < 16; ++k4) {
            float4 p4[4], v4[4];
#pragma unroll
            for (int i = 0; i < 4; ++i) p4[i] = Ks[sw(ty * 4 + i, k4)];
#pragma unroll
            for (int kk = 0; kk < 4; ++kk) v4[kk] = Vs[sw(k4 * 4 + kk, tx)];
#pragma unroll
            for (int i = 0; i < 4; ++i) {
                o[i][0] += p4[i].x*v4[0].x + p4[i].y*v4[1].x + p4[i].z*v4[2].x + p4[i].w*v4[3].x;
                o[i][1] += p4[i].x*v4[0].y + p4[i].y*v4[1].y + p4[i].z*v4[2].y + p4[i].w*v4[3].y;
                o[i][2] += p4[i].x*v4[0].z + p4[i].y*v4[1].z + p4[i].z*v4[2].z + p4[i].w*v4[3].z;
                o[i][3] += p4[i].x*v4[0].w + p4[i].y*v4[1].w + p4[i].z*v4[2].w + p4[i].w*v4[3].w;
            }
        }
    }

    // ---- epilogue: normalize and store ----
#pragma unroll
    for (int i = 0; i < 4; ++i) {
        const float inv = 1.0f / l[i];
        const int row = q0 + ty * 4 + i;
        out[(base + row) * 16 + tx] =
            make_float4(o[i][0] * inv, o[i][1] * inv, o[i][2] * inv, o[i][3] * inv);
    }
}

// ---------------------------------------------------------------------------
// Launch
// ---------------------------------------------------------------------------
extern "C" void kernel_launch(void* const* d_in, const int* in_sizes, int n_in,
                              void* d_out, int out_size)
{
    (void)in_sizes; (void)n_in; (void)out_size;
    const float4* x  = (const float4*)d_in[0];
    const float4* Wq = (const float4*)d_in[1];
    const float*  bq = (const float*) d_in[2];
    const float4* Wk = (const float4*)d_in[3];
    const float*  bk = (const float*) d_in[4];
    const float4* Wv = (const float4*)d_in[5];
    const float*  bv = (const float*) d_in[6];

    dim3 g1(BSROWS / 64, 3);
    qkv_kernel<<<g1, 256>>>(x, Wq, bq, Wk, bk, Wv, bv);

    dim3 g2(S_ / 64, B_);
    attn_kernel<<<g2, 256>>>((float4*)d_out);
}

// round 10
// speedup vs baseline: 1.3685x; 1.0919x over previous
#include <cuda_runtime.h>

// Problem constants
#define B_   8
#define S_   4096
#define H_   1024
#define D_   64
#define BSROWS (B_ * S_)   // 32768 rows

typedef unsigned long long u64;

// Scratch Q/K/V (device globals — no allocation allowed).
__device__ float4 g_Q[BSROWS * 16];
__device__ float4 g_K[BSROWS * 16];
__device__ float4 g_V[BSROWS * 16];

// XOR swizzle at float4 granularity, keyed on the ROW QUAD (row>>2).
__device__ __forceinline__ int sw(int row, int c4) {
    return row * 16 + (c4 ^ ((row >> 2) & 15));
}

// ---- packed f32x2 helpers (FFMA2: 2 FLOPs per issue slot) ----
__device__ __forceinline__ u64 pack2(float x, float y) {
    u64 r; asm("mov.b64 %0, {%1,%2};" : "=l"(r) : "f"(x), "f"(y)); return r;
}
__device__ __forceinline__ float2 unpack2(u64 v) {
    float2 r; asm("mov.b64 {%0,%1}, %2;" : "=f"(r.x), "=f"(r.y) : "l"(v)); return r;
}
__device__ __forceinline__ void fma2(u64& d, u64 a, u64 b) {
    asm("fma.rn.f32x2 %0, %1, %2, %0;" : "+l"(d) : "l"(a), "l"(b));
}
__device__ __forceinline__ void mul2(u64& d, u64 a) {
    asm("mul.rn.f32x2 %0, %0, %1;" : "+l"(d) : "l"(a));
}

// ---------------------------------------------------------------------------
// Kernel 1: QKV projection.  out[r][d] = sum_h x[r][h] * W[h][d] + b[d]
// grid = (BSROWS/64, 3), block = 256.  64x64 tile; packed-f32x2 inner loop.
// ---------------------------------------------------------------------------
__global__ __launch_bounds__(256, 2)
void qkv_kernel(const float4* __restrict__ x,
                const float4* __restrict__ Wq, const float* __restrict__ bq,
                const float4* __restrict__ Wk, const float* __restrict__ bk,
                const float4* __restrict__ Wv, const float* __restrict__ bv)
{
    __shared__ float4 As[64 * 16];   // x tile   [row][k]  (swizzled)
    __shared__ float4 Bs[64 * 16];   // W tile   [k][d]    (swizzled)
    const ulonglong2* Bs2 = reinterpret_cast<const ulonglong2*>(Bs);

    const int tid = threadIdx.x;
    const int ty  = tid >> 4;
    const int tx  = tid & 15;
    const int r0  = blockIdx.x * 64;

    const float4* W; const float* bias; float4* out;
    if (blockIdx.y == 0)      { W = Wq; bias = bq; out = g_Q; }
    else if (blockIdx.y == 1) { W = Wk; bias = bk; out = g_K; }
    else                      { W = Wv; bias = bv; out = g_V; }

    // acc2[i][0] = cols {0,1}, acc2[i][1] = cols {2,3} of this thread's 4x4
    u64 acc2[4][2];
#pragma unroll
    for (int i = 0; i < 4; ++i) { acc2[i][0] = 0ull; acc2[i][1] = 0ull; }

    for (int kt = 0; kt < 16; ++kt) {
        __syncthreads();
#pragma unroll
        for (int p = 0; p < 4; ++p) {
            int idx = tid + p * 256;
            int row = idx >> 4, c4 = idx & 15;
            As[sw(row, c4)] = x[(size_t)(r0 + row) * 256 + kt * 16 + c4];
            Bs[sw(row, c4)] = W[(size_t)(kt * 64 + row) * 16 + c4];
        }
        __syncthreads();

#pragma unroll 4
        for (int k4 = 0; k4 < 16; ++k4) {
            float4 a4[4]; ulonglong2 b2[4];
#pragma unroll
            for (int i = 0; i < 4; ++i) a4[i] = As[sw(ty * 4 + i, k4)];
#pragma unroll
            for (int kk = 0; kk < 4; ++kk) b2[kk] = Bs2[sw(k4 * 4 + kk, tx)];
#pragma unroll
            for (int i = 0; i < 4; ++i) {
                u64 p0 = pack2(a4[i].x, a4[i].x);
                fma2(acc2[i][0], p0, b2[0].x); fma2(acc2[i][1], p0, b2[0].y);
                u64 p1 = pack2(a4[i].y, a4[i].y);
                fma2(acc2[i][0], p1, b2[1].x); fma2(acc2[i][1], p1, b2[1].y);
                u64 p2 = pack2(a4[i].z, a4[i].z);
                fma2(acc2[i][0], p2, b2[2].x); fma2(acc2[i][1], p2, b2[2].y);
                u64 p3 = pack2(a4[i].w, a4[i].w);
                fma2(acc2[i][0], p3, b2[3].x); fma2(acc2[i][1], p3, b2[3].y);
            }
        }
    }

    const float b0 = bias[tx * 4 + 0], b1 = bias[tx * 4 + 1];
    const float b2_ = bias[tx * 4 + 2], b3 = bias[tx * 4 + 3];
#pragma unroll
    for (int i = 0; i < 4; ++i) {
        float2 lo = unpack2(acc2[i][0]), hi = unpack2(acc2[i][1]);
        int row = r0 + ty * 4 + i;
        out[(size_t)row * 16 + tx] =
            make_float4(lo.x + b0, lo.y + b1, hi.x + b2_, hi.y + b3);
    }
}

// ---------------------------------------------------------------------------
// Kernel 2: causal flash attention, fp32, packed-f32x2 math.
// grid = (S/64, B), block = 256 (16x16, 4x4 per thread).
// ---------------------------------------------------------------------------
__global__ __launch_bounds__(256, 2)
void attn_kernel(float4* __restrict__ out)
{
    __shared__ float4 Qs[64 * 16];
    __shared__ float4 Ks[64 * 16];   // reused as P after S is computed
    __shared__ float4 Vs[64 * 16];
    const ulonglong2* Q2 = reinterpret_cast<const ulonglong2*>(Qs);
    const ulonglong2* K2 = reinterpret_cast<const ulonglong2*>(Ks);
    const ulonglong2* V2 = reinterpret_cast<const ulonglong2*>(Vs);

    const int tid = threadIdx.x;
    const int ty  = tid >> 4;
    const int tx  = tid & 15;
    const int qt  = (int)(gridDim.x - 1) - (int)blockIdx.x;  // heavy blocks first
    const int b   = blockIdx.y;
    const int q0  = qt * 64;
    const size_t base = (size_t)b * S_;

    // Load Q tile once
#pragma unroll
    for (int p = 0; p < 4; ++p) {
        int idx = tid + p * 256;
        int row = idx >> 4, c4 = idx & 15;
        Qs[sw(row, c4)] = g_Q[(base + q0 + row) * 16 + c4];
    }

    // o2[i][0] = out cols {0,1}, o2[i][1] = cols {2,3} (packed f32x2)
    u64 o2[4][2];
    float m[4], l[4];
#pragma unroll
    for (int i = 0; i < 4; ++i) {
        m[i] = -1e30f; l[i] = 0.0f; o2[i][0] = 0ull; o2[i][1] = 0ull;
    }
    const float scale = 0.125f;   // 1/sqrt(64)

    for (int t = 0; t <= qt; ++t) {
        const int k0 = t * 64;
        __syncthreads();
#pragma unroll
        for (int p = 0; p < 4; ++p) {
            int idx = tid + p * 256;
            int row = idx >> 4, c4 = idx & 15;
            Ks[sw(row, c4)] = g_K[(base + k0 + row) * 16 + c4];
            Vs[sw(row, c4)] = g_V[(base + k0 + row) * 16 + c4];
        }
        __syncthreads();

        // ---- S = Q K^T : packed accumulation, horizontal add at the end ----
        u64 acc2[4][4];
#pragma unroll
        for (int i = 0; i < 4; ++i)
#pragma unroll
            for (int j = 0; j < 4; ++j) acc2[i][j] = 0ull;

#pragma unroll 4
        for (int k4 = 0; k4 < 16; ++k4) {
            ulonglong2 a2[4], b2[4];
#pragma unroll
            for (int i = 0; i < 4; ++i) a2[i] = Q2[sw(ty * 4 + i, k4)];
#pragma unroll
            for (int j = 0; j < 4; ++j) b2[j] = K2[sw(tx * 4 + j, k4)];
#pragma unroll
            for (int i = 0; i < 4; ++i)
#pragma unroll
                for (int j = 0; j < 4; ++j) {
                    fma2(acc2[i][j], a2[i].x, b2[j].x);
                    fma2(acc2[i][j], a2[i].y, b2[j].y);
                }
        }

        float s[4][4];
#pragma unroll
        for (int i = 0; i < 4; ++i)
#pragma unroll
            for (int j = 0; j < 4; ++j) {
                float2 f = unpack2(acc2[i][j]);
                s[i][j] = f.x + f.y;
            }

        // ---- causal mask (diagonal tile only) ----
        if (t == qt) {
#pragma unroll
            for (int i = 0; i < 4; ++i)
#pragma unroll
                for (int j = 0; j < 4; ++j)
                    if (tx * 4 + j > ty * 4 + i) s[i][j] = -1e30f;
        }

        // ---- online softmax (scale folded into exp) ----
#pragma unroll
        for (int i = 0; i < 4; ++i) {
            float rm = fmaxf(fmaxf(s[i][0], s[i][1]), fmaxf(s[i][2], s[i][3]));
#pragma unroll
            for (int off = 1; off < 16; off <<= 1)
                rm = fmaxf(rm, __shfl_xor_sync(0xffffffffu, rm, off, 16));
            const float mn = fmaxf(m[i], rm);
            const float alpha = __expf(scale * (m[i] - mn));
            m[i] = mn;
            float rs = 0.0f;
#pragma unroll
            for (int j = 0; j < 4; ++j) {
                s[i][j] = __expf(scale * (s[i][j] - mn));   // s becomes P
                rs += s[i][j];
            }
#pragma unroll
            for (int off = 1; off < 16; off <<= 1)
                rs += __shfl_xor_sync(0xffffffffu, rs, off, 16);
            l[i] = l[i] * alpha + rs;
            const u64 aa = pack2(alpha, alpha);
            mul2(o2[i][0], aa);
            mul2(o2[i][1], aa);
        }

        __syncthreads();          // all warps done reading Ks as K
        // ---- store P into Ks buffer ----
#pragma unroll
        for (int i = 0; i < 4; ++i)
            Ks[sw(ty * 4 + i, tx)] = make_float4(s[i][0], s[i][1], s[i][2], s[i][3]);
        __syncthreads();

        // ---- O += P @ V : packed f32x2 with broadcast P ----
#pragma unroll 4
        for (int k4 = 0; k4 < 16; ++k4) {
            float4 p4[4]; ulonglong2 v2[4];
#pragma unroll
            for (int i = 0; i < 4; ++i) p4[i] = Ks[sw(ty * 4 + i, k4)];
#pragma unroll
            for (int kk = 0; kk < 4; ++kk) v2[kk] = V2[sw(k4 * 4 + kk, tx)];
#pragma unroll
            for (int i = 0; i < 4; ++i) {
                u64 p0 = pack2(p4[i].x, p4[i].x);
                fma2(o2[i][0], p0, v2[0].x); fma2(o2[i][1], p0, v2[0].y);
                u64 p1 = pack2(p4[i].y, p4[i].y);
                fma2(o2[i][0], p1, v2[1].x); fma2(o2[i][1], p1, v2[1].y);
                u64 p2 = pack2(p4[i].z, p4[i].z);
                fma2(o2[i][0], p2, v2[2].x); fma2(o2[i][1], p2, v2[2].y);
                u64 p3 = pack2(p4[i].w, p4[i].w);
                fma2(o2[i][0], p3, v2[3].x); fma2(o2[i][1], p3, v2[3].y);
            }
        }
    }

    // ---- epilogue: normalize and store ----
#pragma unroll
    for (int i = 0; i < 4; ++i) {
        const float inv = 1.0f / l[i];
        float2 lo = unpack2(o2[i][0]), hi = unpack2(o2[i][1]);
        const int row = q0 + ty * 4 + i;
        out[(base + row) * 16 + tx] =
            make_float4(lo.x * inv, lo.y * inv, hi.x * inv, hi.y * inv);
    }
}

// ---------------------------------------------------------------------------
// Launch
// ---------------------------------------------------------------------------
extern "C" void kernel_launch(void* const* d_in, const int* in_sizes, int n_in,
                              void* d_out, int out_size)
{
    (void)in_sizes; (void)n_in; (void)out_size;
    const float4* x  = (const float4*)d_in[0];
    const float4* Wq = (const float4*)d_in[1];
    const float*  bq = (const float*) d_in[2];
    const float4* Wk = (const float4*)d_in[3];
    const float*  bk = (const float*) d_in[4];
    const float4* Wv = (const float4*)d_in[5];
    const float*  bv = (const float*) d_in[6];

    dim3 g1(BSROWS / 64, 3);
    qkv_kernel<<<g1, 256>>>(x, Wq, bq, Wk, bk, Wv, bv);

    dim3 g2(S_ / 64, B_);
    attn_kernel<<<g2, 256>>>((float4*)d_out);
}